// round 3
// baseline (speedup 1.0000x reference)
#include <cuda_runtime.h>
#include <cstdint>

#define HH 2160
#define WW 3840
#define NS 512
#define ADJ_ELEMS (NS * NS)

#define TILE_W 128
#define TILE_H 48
#define SUB_H  16
#define NSUB   (TILE_H / SUB_H)
#define NWARP  16

// Global accumulators: g_a[s] = (cnt << 40) | sum_y ; g_b[s] = sum_x
__device__ unsigned long long g_a[NS];
__device__ unsigned long long g_b[NS];

// ---------------------------------------------------------------------------
// Kernel 1: zero adjacency region (vectorized) + global accumulators.
// ---------------------------------------------------------------------------
__global__ void zero_kernel(float4* __restrict__ out) {
    int idx = blockIdx.x * blockDim.x + threadIdx.x;   // 65536 float4 = 1MB
    out[idx] = make_float4(0.f, 0.f, 0.f, 0.f);
    if (idx < NS) {
        g_a[idx] = 0ULL;
        g_b[idx] = 0ULL;
    }
}

// ---------------------------------------------------------------------------
// Kernel 2: main scan.
// 512 threads, warp w handles row (sub*16 + w) of each 128x16 sub-tile;
// lane l handles 4 consecutive pixels via one int4 load.
//
// Histogram: 16 warp-PRIVATE smem histograms (32KB). Per pixel:
//   v = 1 | (dx << 9)   (count in [0:9), sum-dx in [9:32); per-warp per
//   sub-tile a bin sees <=128 px, sum-dx <= 128*127 = 16256 -> fits)
// Intra-warp duplicate bins are combined exactly with match_any + redux;
// only group leaders perform the non-atomic LDS+IADD+STS (distinct
// addresses, program-ordered within a warp, private per warp -> race-free).
// dy == warp id (constant per warp per sub-tile), reconstructed at flush.
//
// Adjacency: idempotent __stcg stores of 1.0f; image borders replicate ->
// equal labels -> no store.
// ---------------------------------------------------------------------------
__global__ __launch_bounds__(512) void main_kernel(const int* __restrict__ seg,
                                                   float* __restrict__ adj) {
    __shared__ unsigned int hist[NWARP * NS];
    const int t    = threadIdx.x;
    const int lane = t & 31;
    const int wrp  = t >> 5;                 // 0..15 : row within sub-tile (dy)
    const int x0   = blockIdx.x * TILE_W;
    const int y0   = blockIdx.y * TILE_H;
    const unsigned int lanemask_lt = (1u << lane) - 1u;

    for (int i = t; i < NWARP * NS; i += 512) hist[i] = 0u;

    unsigned int cnt_r = 0u, sx_r = 0u, sy_r = 0u;
    __syncthreads();

    const int xg = x0 + lane * 4;
    unsigned int vj[4];
#pragma unroll
    for (int j = 0; j < 4; ++j)
        vj[j] = 1u | ((unsigned int)(lane * 4 + j) << 9);

    unsigned int* const myhist = hist + wrp * NS;

#pragma unroll
    for (int sub = 0; sub < NSUB; ++sub) {
        const int yg = y0 + sub * SUB_H + wrp;
        const int* row = seg + (size_t)yg * WW + xg;

        const int4 self = *(const int4*)row;

        // Right neighbor of element 3 = next lane's element 0.
        int nr = __shfl_down_sync(0xffffffffu, self.x, 1);
        if (lane == 31)
            nr = (xg + 4 < WW) ? row[4] : self.w;   // replicate at x edge

        int4 dn;
        if (yg + 1 < HH) dn = *(const int4*)(row + WW);
        else             dn = self;                  // replicate at y edge

        const int sv[4] = {self.x, self.y, self.z, self.w};
        const int rv[4] = {self.y, self.z, self.w, nr};
        const int dv[4] = {dn.x, dn.y, dn.z, dn.w};

#pragma unroll
        for (int j = 0; j < 4; ++j) {
            const int s = sv[j];
            // exact intra-warp aggregation of same-bin lanes
            const unsigned int m   = __match_any_sync(0xffffffffu, s);
            const unsigned int sum = __reduce_add_sync(m, vj[j]);
            if ((m & lanemask_lt) == 0u)      // lowest lane of group = leader
                myhist[s] += sum;             // non-atomic RMW, race-free
            const int base = s * NS;
            if (s != rv[j]) __stcg(&adj[base + rv[j]], 1.0f);
            if (s != dv[j]) __stcg(&adj[base + dv[j]], 1.0f);
        }

        __syncthreads();
        // Flush: thread t owns bin t; gather across the 16 warp histograms.
        {
            unsigned int c_s = 0u, sy_s = 0u, sx_s = 0u;
#pragma unroll
            for (int w = 0; w < NWARP; ++w) {
                const unsigned int v = hist[w * NS + t];
                hist[w * NS + t] = 0u;
                const unsigned int c = v & 511u;
                c_s  += c;
                sy_s += c * (unsigned int)w;
                sx_s += v >> 9;
            }
            cnt_r += c_s;
            sy_r  += sy_s + c_s * (unsigned int)(sub * SUB_H);
            sx_r  += sx_s;
        }
        __syncthreads();
    }

    // Per-block flush: 2 u64 REDG per bin.
    const unsigned long long sy_abs =
        (unsigned long long)sy_r + (unsigned long long)cnt_r * (unsigned long long)y0;
    const unsigned long long sx_abs =
        (unsigned long long)sx_r + (unsigned long long)cnt_r * (unsigned long long)x0;
    atomicAdd(&g_a[t], ((unsigned long long)cnt_r << 40) | sy_abs);
    atomicAdd(&g_b[t], sx_abs);
}

// ---------------------------------------------------------------------------
// Kernel 3: centers[s] = (sum_x / cnt, sum_y / cnt)
// ---------------------------------------------------------------------------
__global__ void centers_kernel(float* __restrict__ out) {
    int s = blockIdx.x * blockDim.x + threadIdx.x;
    if (s < NS) {
        const unsigned long long a = g_a[s];
        const double c  = (double)(a >> 40);
        const double sy = (double)(a & ((1ULL << 40) - 1ULL));
        const double sx = (double)g_b[s];
        out[ADJ_ELEMS + 2 * s + 0] = (float)(sx / c);
        out[ADJ_ELEMS + 2 * s + 1] = (float)(sy / c);
    }
}

extern "C" void kernel_launch(void* const* d_in, const int* in_sizes, int n_in,
                              void* d_out, int out_size) {
    const int* seg = (const int*)d_in[0];
    float* out = (float*)d_out;

    zero_kernel<<<ADJ_ELEMS / 4 / 256, 256>>>((float4*)out);

    dim3 grid(WW / TILE_W, HH / TILE_H);   // 30 x 45 = 1350 blocks
    main_kernel<<<grid, 512>>>(seg, out);

    centers_kernel<<<1, NS>>>(out);
}

// round 4
// speedup vs baseline: 1.4030x; 1.4030x over previous
#include <cuda_runtime.h>
#include <cstdint>

#define HH 2160
#define WW 3840
#define NS 512
#define ADJ_ELEMS (NS * NS)

#define NCOPY 128                 // privatized global histogram copies
#define STRIP 9                   // rows per warp strip
#define WARPS 8                   // warps per block
#define TILE_H (STRIP * WARPS)    // 72 rows per block
// grid: x = 3840/128 = 30, y = 2160/72 = 30  -> 900 blocks

// Packed per-segment accumulators, privatized: [copy][bin]
//   bits [42:64) count, [21:42) sum_x (global), [0:21) sum_y (global)
__device__ unsigned long long g_hist[NCOPY * NS];

// ---------------------------------------------------------------------------
// Kernel 1: zero adjacency region + histogram copies (vectorized).
// ---------------------------------------------------------------------------
__global__ void zero_kernel(float4* __restrict__ out) {
    int idx = blockIdx.x * blockDim.x + threadIdx.x;  // 98304 x 16B
    if (idx < ADJ_ELEMS / 4) {
        out[idx] = make_float4(0.f, 0.f, 0.f, 0.f);
    } else {
        ((ulonglong2*)g_hist)[idx - ADJ_ELEMS / 4] = make_ulonglong2(0ULL, 0ULL);
    }
}

// ---------------------------------------------------------------------------
// Kernel 2: main scan. 256 threads, warp w owns a 128(x) x 9(y) strip,
// lane l owns 4 consecutive pixels per row (one int4 load), rows walked
// sequentially with the "down" row carried into the next iteration's "self".
//
// Centroids: ONE fire-and-forget u64 red.add per pixel into a privatized
// global histogram copy (L2-resident). No smem, no syncthreads.
// Adjacency: idempotent __stcg 1.0f stores; image borders replicate ->
// equal labels -> no store.
// ---------------------------------------------------------------------------
__global__ __launch_bounds__(256) void main_kernel(const int* __restrict__ seg,
                                                   float* __restrict__ adj) {
    const int t    = threadIdx.x;
    const int lane = t & 31;
    const int wrp  = t >> 5;                       // 0..7
    const int x0   = blockIdx.x * 128;
    const int xg   = x0 + lane * 4;
    const int ys   = blockIdx.y * TILE_H + wrp * STRIP;   // strip start row

    const int copy = (blockIdx.y * gridDim.x + blockIdx.x) & (NCOPY - 1);
    unsigned long long* const hc = g_hist + copy * NS;

    // per-pixel packed values minus the y term
    unsigned long long vx[4];
#pragma unroll
    for (int j = 0; j < 4; ++j)
        vx[j] = (1ULL << 42) | ((unsigned long long)(xg + j) << 21);

    const int* rowp = seg + (size_t)ys * WW + xg;
    int4 self = *(const int4*)rowp;

    for (int r = 0; r < STRIP; ++r) {
        const int yg = ys + r;
        rowp += WW;
        int4 dn;
        if (yg + 1 < HH) dn = *(const int4*)rowp;   // next row (down nbr)
        else             dn = self;                 // replicate at y edge

        // Right neighbor of element 3 = next lane's element 0.
        int nr = __shfl_down_sync(0xffffffffu, self.x, 1);
        if (lane == 31)
            nr = (xg + 4 < WW) ? rowp[4 - WW] : self.w;  // current row scalar

        const int sv[4] = {self.x, self.y, self.z, self.w};
        const int rv[4] = {self.y, self.z, self.w, nr};
        const int dv[4] = {dn.x, dn.y, dn.z, dn.w};

        const unsigned long long yterm = (unsigned long long)yg;
#pragma unroll
        for (int j = 0; j < 4; ++j) {
            const int s = sv[j];
            atomicAdd(&hc[s], vx[j] + yterm);       // REDG.64, no return
            const int base = s * NS;
            if (s != rv[j]) __stcg(&adj[base + rv[j]], 1.0f);
            if (s != dv[j]) __stcg(&adj[base + dv[j]], 1.0f);
        }
        self = dn;
    }
}

// ---------------------------------------------------------------------------
// Kernel 3: reduce histogram copies -> centers.
// 512 blocks (one per bin) x 32 threads; lane k sums copies k, k+32, ...
// ---------------------------------------------------------------------------
__global__ void centers_kernel(float* __restrict__ out) {
    const int s    = blockIdx.x;
    const int lane = threadIdx.x;
    unsigned int cnt = 0u, sx = 0u, sy = 0u;
#pragma unroll
    for (int k = 0; k < NCOPY / 32; ++k) {
        const unsigned long long v = g_hist[(lane + k * 32) * NS + s];
        cnt += (unsigned int)(v >> 42);
        sx  += (unsigned int)((v >> 21) & 0x1FFFFFu);
        sy  += (unsigned int)(v & 0x1FFFFFu);
    }
#pragma unroll
    for (int off = 16; off > 0; off >>= 1) {
        cnt += __shfl_xor_sync(0xffffffffu, cnt, off);
        sx  += __shfl_xor_sync(0xffffffffu, sx, off);
        sy  += __shfl_xor_sync(0xffffffffu, sy, off);
    }
    if (lane == 0) {
        const double c = (double)cnt;
        out[ADJ_ELEMS + 2 * s + 0] = (float)((double)sx / c);
        out[ADJ_ELEMS + 2 * s + 1] = (float)((double)sy / c);
    }
}

extern "C" void kernel_launch(void* const* d_in, const int* in_sizes, int n_in,
                              void* d_out, int out_size) {
    const int* seg = (const int*)d_in[0];
    float* out = (float*)d_out;

    // 1MB adj + 512KB hist = 98304 x 16B
    zero_kernel<<<(ADJ_ELEMS / 4 + NCOPY * NS / 2 + 255) / 256, 256>>>((float4*)out);

    dim3 grid(WW / 128, HH / TILE_H);   // 30 x 30 = 900 blocks
    main_kernel<<<grid, 256>>>(seg, out);

    centers_kernel<<<NS, 32>>>(out);
}